// round 7
// baseline (speedup 1.0000x reference)
#include <cuda_runtime.h>
#include <cuda_bf16.h>

// LengthRegulator, fused single kernel (v3).
//   x:        (B=32, C=384, T=1024) float32
//   duration: (B, T) int32
// Output 0: out (B, C+2, ML=8192) float32
// Output 1: mel_len (B,) as float32 values at tail of d_out
//
// v3 changes vs v2 (96.1us):
//  - __launch_bounds__(256,7): regs<=36 -> 7 blocks/SM -> all 1024 blocks
//    resident in ONE wave (148*7=1036), no tail wave.
//  - fi/len computed AFTER the channel loop (s_end persists) -> fewer live regs.
//  - loop specialization: all-valid (no predicates), all-invalid (stores only,
//    zero gather loads), mixed (rare boundary threads).

#define LR_B   32
#define LR_C   384
#define LR_T   1024
#define LR_ML  8192
#define LR_MAXDUR 10000
#define LR_PCH 1024   // positions per chunk
#define LR_CPG 96     // channels per c-group (384/4)

__device__ __forceinline__ int lr_clip(int v) {
    v = v < 0 ? -v : v;
    return v < 1 ? 1 : (v > LR_MAXDUR ? LR_MAXDUR : v);
}

__global__ __launch_bounds__(256, 7) void lr_fused_kernel(
    const float* __restrict__ x,
    const int* __restrict__ duration,
    float* __restrict__ out,
    long long out_size)
{
    const int chunk = blockIdx.x;   // 0..7
    const int b     = blockIdx.y;   // 0..31
    const int cg    = blockIdx.z;   // 0..3
    const int tid   = threadIdx.x;
    const int lane  = tid & 31;
    const int wrp   = tid >> 5;

    __shared__ int s_end[LR_T + 1]; // inclusive cumsum of clipped durations + sentinel
    __shared__ int s_wsum[8];

    // ---- load 4 durations (16B vectorized), clip, local cumsums ----
    int4 dv = *reinterpret_cast<const int4*>(duration + b * LR_T + tid * 4);
    int d0 = lr_clip(dv.x);
    int d1 = lr_clip(dv.y);
    int d2 = lr_clip(dv.z);
    int d3 = lr_clip(dv.w);
    int c0 = d0, c1 = c0 + d1, c2 = c1 + d2, c3 = c2 + d3;

    // ---- warp inclusive scan of per-thread sums ----
    int v = c3;
    #pragma unroll
    for (int off = 1; off < 32; off <<= 1) {
        int n = __shfl_up_sync(0xffffffffu, v, off);
        if (lane >= off) v += n;
    }
    int wexcl = v - c3;               // exclusive prefix within warp
    if (lane == 31) s_wsum[wrp] = v;  // warp total
    __syncthreads();
    if (tid == 0) {
        int acc = 0;
        #pragma unroll
        for (int i = 0; i < 8; ++i) { int t = s_wsum[i]; s_wsum[i] = acc; acc += t; }
        s_end[LR_T] = 0x7fffffff;     // sentinel for incremental search
    }
    __syncthreads();
    const int base = s_wsum[wrp] + wexcl;
    s_end[tid * 4 + 0] = base + c0;
    s_end[tid * 4 + 1] = base + c1;
    s_end[tid * 4 + 2] = base + c2;
    s_end[tid * 4 + 3] = base + c3;
    __syncthreads();

    const int total = s_end[LR_T - 1];

    // mel_len (float values) from one block per batch
    if (chunk == 0 && cg == 0 && tid == 0) {
        long long main_elems = (long long)LR_B * (LR_C + 2) * LR_ML;
        if (out_size >= main_elems + LR_B) out[main_elems + b] = (float)total;
    }

    // ---- searchsorted(right) for 4 consecutive positions ----
    const int pos0 = chunk * LR_PCH + tid * 4;

    int lo = 0;  // count of ends <= pos0
    #pragma unroll
    for (int step = 512; step > 0; step >>= 1)
        if (s_end[lo + step - 1] <= pos0) lo += step;
    const int t0 = lo;
    const int t1 = t0 + (s_end[t0] <= pos0 + 1);
    const int t2 = t1 + (s_end[t1] <= pos0 + 2);
    const int t3 = t2 + (s_end[t2] <= pos0 + 3);

    // ---- channel streaming: 96 rows ----
    const float* xb = x + (size_t)b * LR_C * LR_T;
    float* ob = out + (size_t)b * (LR_C + 2) * LR_ML + pos0;
    const int cbase = cg * LR_CPG;

    if (pos0 + 3 < total) {
        // fast path: all 4 positions valid -> pure gathers, no predicates
        #pragma unroll 4
        for (int c = cbase; c < cbase + LR_CPG; ++c) {
            const float* xr = xb + (size_t)c * LR_T;
            float4 w;
            w.x = __ldg(xr + t0);
            w.y = __ldg(xr + t1);
            w.z = __ldg(xr + t2);
            w.w = __ldg(xr + t3);
            *reinterpret_cast<float4*>(ob + (size_t)c * LR_ML) = w;
        }
    } else if (pos0 >= total) {
        // tail path: all invalid -> zero stores, NO gather loads
        const float4 z = make_float4(0.f, 0.f, 0.f, 0.f);
        #pragma unroll 8
        for (int c = cbase; c < cbase + LR_CPG; ++c) {
            *reinterpret_cast<float4*>(ob + (size_t)c * LR_ML) = z;
        }
    } else {
        // boundary thread (rare): predicated
        const bool v0 = pos0     < total;
        const bool v1 = pos0 + 1 < total;
        const bool v2 = pos0 + 2 < total;
        const bool v3 = pos0 + 3 < total;
        #pragma unroll 4
        for (int c = cbase; c < cbase + LR_CPG; ++c) {
            const float* xr = xb + (size_t)c * LR_T;
            float4 w;
            w.x = v0 ? __ldg(xr + t0) : 0.0f;
            w.y = v1 ? __ldg(xr + t1) : 0.0f;
            w.z = v2 ? __ldg(xr + t2) : 0.0f;
            w.w = v3 ? __ldg(xr + t3) : 0.0f;
            *reinterpret_cast<float4*>(ob + (size_t)c * LR_ML) = w;
        }
    }

    // c-group 3 also emits the idx_in and length rows (computed here, after
    // the hot loop, from still-live s_end)
    if (cg == 3) {
        float fi[4], fl[4];
        const int tt[4] = {t0, t1, t2, t3};
        #pragma unroll
        for (int j = 0; j < 4; ++j) {
            float a = 0.f, l = 0.f;
            if (pos0 + j < total) {
                int tj = tt[j];
                int pv = tj ? s_end[tj - 1] : 0;
                a = (float)(pos0 + j - pv);
                l = (float)(s_end[tj] - pv);
            }
            fi[j] = a; fl[j] = l;
        }
        float4 vi = make_float4(fi[0], fi[1], fi[2], fi[3]);
        float4 vl = make_float4(fl[0], fl[1], fl[2], fl[3]);
        *reinterpret_cast<float4*>(ob + (size_t)LR_C       * LR_ML) = vi;
        *reinterpret_cast<float4*>(ob + (size_t)(LR_C + 1) * LR_ML) = vl;
    }
}

extern "C" void kernel_launch(void* const* d_in, const int* in_sizes, int n_in,
                              void* d_out, int out_size)
{
    const float* x   = (const float*)d_in[0];
    const int*   dur = (const int*)d_in[1];
    float*       out = (float*)d_out;

    dim3 grid(LR_ML / LR_PCH, LR_B, 4);
    lr_fused_kernel<<<grid, 256>>>(x, dur, out, (long long)out_size);
}

// round 8
// speedup vs baseline: 1.2089x; 1.2089x over previous
#include <cuda_runtime.h>
#include <cuda_bf16.h>

// LengthRegulator, fused single kernel (v4).
//   x:        (B=32, C=384, T=1024) float32
//   duration: (B, T) int32
// Output 0: out (B, C+2, ML=8192) float32
// Output 1: mel_len (B,) as float32 values at tail of d_out
//
// v4 vs v2 (96.1us best): finer grid for load balance (12 channel-groups of
// 32 rows -> 3072 blocks, ~3.5 waves; v3 proved single-wave residency loses
// to block-duration imbalance), streaming stores (__stcs) to keep x in L2.
// Loop body identical to v2 (predicated gathers, unroll 4) plus the
// zero-store tail path.

#define LR_B   32
#define LR_C   384
#define LR_T   1024
#define LR_ML  8192
#define LR_MAXDUR 10000
#define LR_PCH 1024   // positions per chunk
#define LR_CPG 32     // channels per c-group (384/12)
#define LR_NCG 12     // channel groups

__device__ __forceinline__ int lr_clip(int v) {
    v = v < 0 ? -v : v;
    return v < 1 ? 1 : (v > LR_MAXDUR ? LR_MAXDUR : v);
}

__global__ __launch_bounds__(256) void lr_fused_kernel(
    const float* __restrict__ x,
    const int* __restrict__ duration,
    float* __restrict__ out,
    long long out_size)
{
    const int chunk = blockIdx.x;   // 0..7
    const int b     = blockIdx.y;   // 0..31
    const int cg    = blockIdx.z;   // 0..11
    const int tid   = threadIdx.x;
    const int lane  = tid & 31;
    const int wrp   = tid >> 5;

    __shared__ int s_end[LR_T + 1]; // inclusive cumsum of clipped durations + sentinel
    __shared__ int s_wsum[8];

    // ---- load 4 durations (16B vectorized), clip, local cumsums ----
    int4 dv = *reinterpret_cast<const int4*>(duration + b * LR_T + tid * 4);
    int d0 = lr_clip(dv.x);
    int d1 = lr_clip(dv.y);
    int d2 = lr_clip(dv.z);
    int d3 = lr_clip(dv.w);
    int c0 = d0, c1 = c0 + d1, c2 = c1 + d2, c3 = c2 + d3;

    // ---- warp inclusive scan of per-thread sums ----
    int v = c3;
    #pragma unroll
    for (int off = 1; off < 32; off <<= 1) {
        int n = __shfl_up_sync(0xffffffffu, v, off);
        if (lane >= off) v += n;
    }
    int wexcl = v - c3;               // exclusive prefix within warp
    if (lane == 31) s_wsum[wrp] = v;  // warp total
    __syncthreads();
    if (tid == 0) {
        int acc = 0;
        #pragma unroll
        for (int i = 0; i < 8; ++i) { int t = s_wsum[i]; s_wsum[i] = acc; acc += t; }
        s_end[LR_T] = 0x7fffffff;     // sentinel for incremental search
    }
    __syncthreads();
    const int base = s_wsum[wrp] + wexcl;
    s_end[tid * 4 + 0] = base + c0;
    s_end[tid * 4 + 1] = base + c1;
    s_end[tid * 4 + 2] = base + c2;
    s_end[tid * 4 + 3] = base + c3;
    __syncthreads();

    const int total = s_end[LR_T - 1];

    // mel_len (float values) from one block per batch
    if (chunk == 0 && cg == 0 && tid == 0) {
        long long main_elems = (long long)LR_B * (LR_C + 2) * LR_ML;
        if (out_size >= main_elems + LR_B) out[main_elems + b] = (float)total;
    }

    // ---- searchsorted(right) for 4 consecutive positions ----
    const int pos0 = chunk * LR_PCH + tid * 4;

    int lo = 0;  // count of ends <= pos0
    #pragma unroll
    for (int step = 512; step > 0; step >>= 1)
        if (s_end[lo + step - 1] <= pos0) lo += step;
    const int t0 = lo;
    const int t1 = t0 + (s_end[t0] <= pos0 + 1);
    const int t2 = t1 + (s_end[t1] <= pos0 + 2);
    const int t3 = t2 + (s_end[t2] <= pos0 + 3);

    // ---- channel streaming: 32 rows ----
    const float* xb = x + (size_t)b * LR_C * LR_T;
    float* ob = out + (size_t)b * (LR_C + 2) * LR_ML + pos0;
    const int cbase = cg * LR_CPG;

    if (pos0 >= total) {
        // tail: all 4 positions invalid -> zero stores, no gather loads
        const float4 z = make_float4(0.f, 0.f, 0.f, 0.f);
        #pragma unroll 8
        for (int c = cbase; c < cbase + LR_CPG; ++c) {
            __stcs(reinterpret_cast<float4*>(ob + (size_t)c * LR_ML), z);
        }
    } else {
        const bool v0 = true;                 // pos0 < total here
        const bool v1 = pos0 + 1 < total;
        const bool v2 = pos0 + 2 < total;
        const bool v3 = pos0 + 3 < total;
        #pragma unroll 4
        for (int c = cbase; c < cbase + LR_CPG; ++c) {
            const float* xr = xb + (size_t)c * LR_T;
            float4 w;
            w.x = v0 ? __ldg(xr + t0) : 0.0f;
            w.y = v1 ? __ldg(xr + t1) : 0.0f;
            w.z = v2 ? __ldg(xr + t2) : 0.0f;
            w.w = v3 ? __ldg(xr + t3) : 0.0f;
            __stcs(reinterpret_cast<float4*>(ob + (size_t)c * LR_ML), w);
        }
    }

    // last c-group also emits the idx_in and length rows (from still-live s_end)
    if (cg == LR_NCG - 1) {
        float fi[4], fl[4];
        const int tt[4] = {t0, t1, t2, t3};
        #pragma unroll
        for (int j = 0; j < 4; ++j) {
            float a = 0.f, l = 0.f;
            if (pos0 + j < total) {
                int tj = tt[j];
                int pv = tj ? s_end[tj - 1] : 0;
                a = (float)(pos0 + j - pv);
                l = (float)(s_end[tj] - pv);
            }
            fi[j] = a; fl[j] = l;
        }
        float4 vi = make_float4(fi[0], fi[1], fi[2], fi[3]);
        float4 vl = make_float4(fl[0], fl[1], fl[2], fl[3]);
        __stcs(reinterpret_cast<float4*>(ob + (size_t)LR_C       * LR_ML), vi);
        __stcs(reinterpret_cast<float4*>(ob + (size_t)(LR_C + 1) * LR_ML), vl);
    }
}

extern "C" void kernel_launch(void* const* d_in, const int* in_sizes, int n_in,
                              void* d_out, int out_size)
{
    const float* x   = (const float*)d_in[0];
    const int*   dur = (const int*)d_in[1];
    float*       out = (float*)d_out;

    dim3 grid(LR_ML / LR_PCH, LR_B, LR_NCG);
    lr_fused_kernel<<<grid, 256>>>(x, dur, out, (long long)out_size);
}

// round 9
// speedup vs baseline: 1.3000x; 1.0754x over previous
#include <cuda_runtime.h>
#include <cuda_bf16.h>

// LengthRegulator, fused single kernel (v5).
//   x:        (B=32, C=384, T=1024) float32
//   duration: (B, T) int32
// Output 0: out (B, C+2, ML=8192) float32
// Output 1: mel_len (B,) as float32 values at tail of d_out
//
// v5 vs v4 (88.1us): 24 channel-groups of 16 rows -> 6144 blocks (~7 waves)
// for finer load balancing (v4 proved waves/balance is the binding lever),
// plus loop specialization (fast all-valid / tail zero-store / rare boundary)
// to strip predicates from the hot gather loop. __stcs streaming stores kept.

#define LR_B   32
#define LR_C   384
#define LR_T   1024
#define LR_ML  8192
#define LR_MAXDUR 10000
#define LR_PCH 1024   // positions per chunk
#define LR_CPG 16     // channels per c-group (384/24)
#define LR_NCG 24     // channel groups

__device__ __forceinline__ int lr_clip(int v) {
    v = v < 0 ? -v : v;
    return v < 1 ? 1 : (v > LR_MAXDUR ? LR_MAXDUR : v);
}

__global__ __launch_bounds__(256) void lr_fused_kernel(
    const float* __restrict__ x,
    const int* __restrict__ duration,
    float* __restrict__ out,
    long long out_size)
{
    const int chunk = blockIdx.x;   // 0..7
    const int b     = blockIdx.y;   // 0..31
    const int cg    = blockIdx.z;   // 0..23
    const int tid   = threadIdx.x;
    const int lane  = tid & 31;
    const int wrp   = tid >> 5;

    __shared__ int s_end[LR_T + 1]; // inclusive cumsum of clipped durations + sentinel
    __shared__ int s_wsum[8];

    // ---- load 4 durations (16B vectorized), clip, local cumsums ----
    int4 dv = *reinterpret_cast<const int4*>(duration + b * LR_T + tid * 4);
    int d0 = lr_clip(dv.x);
    int d1 = lr_clip(dv.y);
    int d2 = lr_clip(dv.z);
    int d3 = lr_clip(dv.w);
    int c0 = d0, c1 = c0 + d1, c2 = c1 + d2, c3 = c2 + d3;

    // ---- warp inclusive scan of per-thread sums ----
    int v = c3;
    #pragma unroll
    for (int off = 1; off < 32; off <<= 1) {
        int n = __shfl_up_sync(0xffffffffu, v, off);
        if (lane >= off) v += n;
    }
    int wexcl = v - c3;               // exclusive prefix within warp
    if (lane == 31) s_wsum[wrp] = v;  // warp total
    __syncthreads();
    if (tid == 0) {
        int acc = 0;
        #pragma unroll
        for (int i = 0; i < 8; ++i) { int t = s_wsum[i]; s_wsum[i] = acc; acc += t; }
        s_end[LR_T] = 0x7fffffff;     // sentinel for incremental search
    }
    __syncthreads();
    const int base = s_wsum[wrp] + wexcl;
    s_end[tid * 4 + 0] = base + c0;
    s_end[tid * 4 + 1] = base + c1;
    s_end[tid * 4 + 2] = base + c2;
    s_end[tid * 4 + 3] = base + c3;
    __syncthreads();

    const int total = s_end[LR_T - 1];

    // mel_len (float values) from one block per batch
    if (chunk == 0 && cg == 0 && tid == 0) {
        long long main_elems = (long long)LR_B * (LR_C + 2) * LR_ML;
        if (out_size >= main_elems + LR_B) out[main_elems + b] = (float)total;
    }

    // ---- searchsorted(right) for 4 consecutive positions ----
    const int pos0 = chunk * LR_PCH + tid * 4;

    int lo = 0;  // count of ends <= pos0
    #pragma unroll
    for (int step = 512; step > 0; step >>= 1)
        if (s_end[lo + step - 1] <= pos0) lo += step;
    const int t0 = lo;
    const int t1 = t0 + (s_end[t0] <= pos0 + 1);
    const int t2 = t1 + (s_end[t1] <= pos0 + 2);
    const int t3 = t2 + (s_end[t2] <= pos0 + 3);

    // ---- channel streaming: 16 rows ----
    const float* xb = x + (size_t)b * LR_C * LR_T;
    float* ob = out + (size_t)b * (LR_C + 2) * LR_ML + pos0;
    const int cbase = cg * LR_CPG;

    if (pos0 + 3 < total) {
        // fast path: all 4 positions valid -> pure gathers, no predicates
        #pragma unroll 4
        for (int c = cbase; c < cbase + LR_CPG; ++c) {
            const float* xr = xb + (size_t)c * LR_T;
            float4 w;
            w.x = __ldg(xr + t0);
            w.y = __ldg(xr + t1);
            w.z = __ldg(xr + t2);
            w.w = __ldg(xr + t3);
            __stcs(reinterpret_cast<float4*>(ob + (size_t)c * LR_ML), w);
        }
    } else if (pos0 >= total) {
        // tail: all 4 positions invalid -> zero stores, no gather loads
        const float4 z = make_float4(0.f, 0.f, 0.f, 0.f);
        #pragma unroll 8
        for (int c = cbase; c < cbase + LR_CPG; ++c) {
            __stcs(reinterpret_cast<float4*>(ob + (size_t)c * LR_ML), z);
        }
    } else {
        // boundary thread (rare): predicated
        const bool v1 = pos0 + 1 < total;
        const bool v2 = pos0 + 2 < total;
        const bool v3 = pos0 + 3 < total;
        #pragma unroll 4
        for (int c = cbase; c < cbase + LR_CPG; ++c) {
            const float* xr = xb + (size_t)c * LR_T;
            float4 w;
            w.x = __ldg(xr + t0);
            w.y = v1 ? __ldg(xr + t1) : 0.0f;
            w.z = v2 ? __ldg(xr + t2) : 0.0f;
            w.w = v3 ? __ldg(xr + t3) : 0.0f;
            __stcs(reinterpret_cast<float4*>(ob + (size_t)c * LR_ML), w);
        }
    }

    // last c-group also emits the idx_in and length rows (from still-live s_end)
    if (cg == LR_NCG - 1) {
        float fi[4], fl[4];
        const int tt[4] = {t0, t1, t2, t3};
        #pragma unroll
        for (int j = 0; j < 4; ++j) {
            float a = 0.f, l = 0.f;
            if (pos0 + j < total) {
                int tj = tt[j];
                int pv = tj ? s_end[tj - 1] : 0;
                a = (float)(pos0 + j - pv);
                l = (float)(s_end[tj] - pv);
            }
            fi[j] = a; fl[j] = l;
        }
        float4 vi = make_float4(fi[0], fi[1], fi[2], fi[3]);
        float4 vl = make_float4(fl[0], fl[1], fl[2], fl[3]);
        __stcs(reinterpret_cast<float4*>(ob + (size_t)LR_C       * LR_ML), vi);
        __stcs(reinterpret_cast<float4*>(ob + (size_t)(LR_C + 1) * LR_ML), vl);
    }
}

extern "C" void kernel_launch(void* const* d_in, const int* in_sizes, int n_in,
                              void* d_out, int out_size)
{
    const float* x   = (const float*)d_in[0];
    const int*   dur = (const int*)d_in[1];
    float*       out = (float*)d_out;

    dim3 grid(LR_ML / LR_PCH, LR_B, LR_NCG);
    lr_fused_kernel<<<grid, 256>>>(x, dur, out, (long long)out_size);
}